// round 8
// baseline (speedup 1.0000x reference)
#include <cuda_runtime.h>
#include <cuda_bf16.h>
#include <cstdint>
#include <math.h>

#define N 4096
#define D 1024
#define NUM_NEG 100
#define BM 128
#define BN 256
#define NT 16            // K=1024 / 64
#define STAGE_A (BM * 128)            // 16384
#define STAGE_BYTES ((BM + BN) * 128) // 49152
#define DSMEM (3 * STAGE_BYTES)       // 147456

// ---------------- scratch (device globals; no allocation allowed) ----------
__device__ __nv_bfloat16 g_Zall[4 * N * D];
__device__ __nv_bfloat16 g_Hall[4 * N * D];
__device__ __nv_bfloat16 g_Pall[4 * N * D];
__device__ __nv_bfloat16 g_W1bf[D * D];
__device__ __nv_bfloat16 g_W2bf[D * D];
__device__ __nv_bfloat16 g_z1[N * D];
__device__ __nv_bfloat16 g_z2[N * D];
__device__ float g_rowsum[N], g_colsum[N], g_mrow[N], g_mcol[N], g_lse[N];
__device__ double g_s[4];  // [0]=gcl1 logsum, [1]=gcl2 logsum, [2]=pair_sum, [3]=pair_cnt

// ---------------- helpers ---------------------------------------------------
__device__ __forceinline__ uint32_t bf2_pack(float a, float b) {
    __nv_bfloat162 t = __floats2bfloat162_rn(a, b);
    return *reinterpret_cast<uint32_t*>(&t);
}

__device__ __forceinline__ void mma16816(float* c, const uint32_t* a, const uint32_t* b) {
    asm volatile(
        "mma.sync.aligned.m16n8k16.row.col.f32.bf16.bf16.f32 "
        "{%0,%1,%2,%3}, {%4,%5,%6,%7}, {%8,%9}, {%0,%1,%2,%3};"
        : "+f"(c[0]), "+f"(c[1]), "+f"(c[2]), "+f"(c[3])
        : "r"(a[0]), "r"(a[1]), "r"(a[2]), "r"(a[3]), "r"(b[0]), "r"(b[1]));
}

__device__ __forceinline__ void ldsm4(uint32_t* r, uint32_t saddr) {
    asm volatile("ldmatrix.sync.aligned.m8n8.x4.shared.b16 {%0,%1,%2,%3}, [%4];"
                 : "=r"(r[0]), "=r"(r[1]), "=r"(r[2]), "=r"(r[3]) : "r"(saddr));
}

template <int W>
__device__ __forceinline__ void cpwait() {
    asm volatile("cp.async.wait_group %0;" :: "n"(W));
}

// swizzled byte offset inside a rows x 64 bf16 stage tile (rows of 128B, 16B chunks)
__device__ __forceinline__ uint32_t SWZ64(int r, int ch) {
    return (uint32_t)(r * 128 + ((ch ^ (r & 7)) << 4));
}

// load one 64-K stage of A(BM rows) + B(BN rows), 256 threads
__device__ __forceinline__ void ld_stage(
    const __nv_bfloat16* __restrict__ A, const __nv_bfloat16* __restrict__ B,
    int m0, int n0, int kt, uint32_t st, int tid) {
    #pragma unroll
    for (int i = 0; i < (BM * 8) / 256; i++) {
        int idx = tid + i * 256;
        int row = idx >> 3, ch = idx & 7;
        const __nv_bfloat16* g = &A[(size_t)(m0 + row) * D + kt + ch * 8];
        asm volatile("cp.async.cg.shared.global [%0], [%1], 16;"
                     :: "r"(st + SWZ64(row, ch)), "l"(g));
    }
    #pragma unroll
    for (int i = 0; i < (BN * 8) / 256; i++) {
        int idx = tid + i * 256;
        int row = idx >> 3, ch = idx & 7;
        const __nv_bfloat16* g = &B[(size_t)(n0 + row) * D + kt + ch * 8];
        asm volatile("cp.async.cg.shared.global [%0], [%1], 16;"
                     :: "r"(st + STAGE_A + SWZ64(row, ch)), "l"(g));
    }
}

// ---------------- bf16 HMMA NT GEMM (128x256 block, 64x64 per warp) --------
// C[i,j] = sum_k A[i,k]*B[j,k].  MODE 0: +bias+ELU->bf16, 1: +bias->bf16,
// 2: sim epilogue (exp(acc/0.8), rowsum/colsum + pos-masked mrow/mcol)
template <int MODE>
__global__ __launch_bounds__(256, 1)
void mm_bf16_k(const __nv_bfloat16* __restrict__ A, const __nv_bfloat16* __restrict__ B,
               const float* __restrict__ bias, __nv_bfloat16* __restrict__ C,
               const float* __restrict__ pos,
               float* __restrict__ rowsum, float* __restrict__ colsum,
               float* __restrict__ mrow, float* __restrict__ mcol, int Nc) {
    extern __shared__ __align__(16) char dsm[];
    __shared__ float srow[BM], srowm[BM];

    int tid = threadIdx.x;
    int warp = tid >> 5, lane = tid & 31;
    int g = lane >> 2, t4 = lane & 3;
    int wm = (warp >> 2) * 64;   // 2 warp-rows x 64
    int wn = (warp & 3) * 64;    // 4 warp-cols x 64
    int m0 = blockIdx.y * BM, n0 = blockIdx.x * BN;
    uint32_t sb = (uint32_t)__cvta_generic_to_shared(dsm);

    float acc[4][8][4] = {};

    ld_stage(A, B, m0, n0, 0, sb, tid);
    asm volatile("cp.async.commit_group;");
    ld_stage(A, B, m0, n0, 64, sb + STAGE_BYTES, tid);
    asm volatile("cp.async.commit_group;");

    int lr = lane & 15, lc = lane >> 4;
    for (int s = 0; s < NT; s++) {
        if (s < NT - 1) cpwait<1>(); else cpwait<0>();
        __syncthreads();
        if (s + 2 < NT) {
            ld_stage(A, B, m0, n0, (s + 2) * 64, sb + ((s + 2) % 3) * STAGE_BYTES, tid);
            asm volatile("cp.async.commit_group;");
        }
        uint32_t ab = sb + (s % 3) * STAGE_BYTES;
        uint32_t bb = ab + STAGE_A;
        #pragma unroll
        for (int ks = 0; ks < 4; ks++) {
            int ch = ks * 2 + lc;
            uint32_t a[4][4], b[4][4];
            #pragma unroll
            for (int mi = 0; mi < 4; mi++)
                ldsm4(a[mi], ab + SWZ64(wm + mi * 16 + lr, ch));
            #pragma unroll
            for (int nb = 0; nb < 4; nb++)
                ldsm4(b[nb], bb + SWZ64(wn + nb * 16 + lr, ch));
            #pragma unroll
            for (int mi = 0; mi < 4; mi++)
                #pragma unroll
                for (int ni = 0; ni < 8; ni++) {
                    uint32_t bf[2] = { b[ni >> 1][ni & 1], b[ni >> 1][(ni & 1) + 2] };
                    mma16816(acc[mi][ni], a[mi], bf);
                }
        }
    }
    __syncthreads();   // smem reuse barrier (MODE 2 epilogue overlays stage bufs)

    if (MODE == 2) {
        if (tid < BM) { srow[tid] = 0.f; srowm[tid] = 0.f; }
        __syncthreads();
        float rp[4][2] = {}, rpm[4][2] = {};
        #pragma unroll
        for (int mi = 0; mi < 4; mi++) {
            int r0 = m0 + wm + mi * 16 + g;
            int r1 = r0 + 8;
            #pragma unroll
            for (int ni = 0; ni < 8; ni++) {
                int c = n0 + wn + ni * 8 + t4 * 2;
                float e0 = __expf(acc[mi][ni][0] * 1.25f);   // 1/TAU
                float e1 = __expf(acc[mi][ni][1] * 1.25f);
                float e2 = __expf(acc[mi][ni][2] * 1.25f);
                float e3 = __expf(acc[mi][ni][3] * 1.25f);
                acc[mi][ni][0] = e0; acc[mi][ni][1] = e1;
                acc[mi][ni][2] = e2; acc[mi][ni][3] = e3;
                float2 p0 = *(const float2*)&pos[(size_t)r0 * N + c];
                float2 p1 = *(const float2*)&pos[(size_t)r1 * N + c];
                rp[mi][0] += e0 + e1;            rp[mi][1] += e2 + e3;
                rpm[mi][0] += e0 * p0.x + e1 * p0.y;
                rpm[mi][1] += e2 * p1.x + e3 * p1.y;
            }
        }
        #pragma unroll
        for (int mi = 0; mi < 4; mi++) {
            int r = wm + mi * 16 + g;
            atomicAdd(&srow[r], rp[mi][0]);
            atomicAdd(&srow[r + 8], rp[mi][1]);
            atomicAdd(&srowm[r], rpm[mi][0]);
            atomicAdd(&srowm[r + 8], rpm[mi][1]);
        }
        // two 32-col transpose passes: et[col_local][row_local], pitch 65
        float* et = (float*)dsm + warp * (32 * 65);
        #pragma unroll
        for (int half = 0; half < 2; half++) {
            #pragma unroll
            for (int mi = 0; mi < 4; mi++)
                #pragma unroll
                for (int nl = 0; nl < 4; nl++) {
                    int ni = half * 4 + nl;
                    #pragma unroll
                    for (int q = 0; q < 4; q++) {
                        int rl = mi * 16 + g + ((q >= 2) ? 8 : 0);
                        int cl = nl * 8 + t4 * 2 + (q & 1);
                        et[cl * 65 + rl] = acc[mi][ni][q];
                    }
                }
            __syncwarp();
            int c = n0 + wn + half * 32 + lane;
            const float4* pc = (const float4*)&pos[(size_t)c * N + m0 + wm];
            float cs = 0.f, csm = 0.f;
            #pragma unroll
            for (int q = 0; q < 16; q++) {
                float4 m4 = pc[q];
                float a0 = et[lane * 65 + q * 4 + 0];
                float a1 = et[lane * 65 + q * 4 + 1];
                float a2 = et[lane * 65 + q * 4 + 2];
                float a3 = et[lane * 65 + q * 4 + 3];
                cs  += a0 + a1 + a2 + a3;
                csm += a0 * m4.x + a1 * m4.y + a2 * m4.z + a3 * m4.w;
            }
            atomicAdd(&colsum[c], cs);
            atomicAdd(&mcol[c], csm);
            __syncwarp();
        }
        __syncthreads();
        if (tid < BM) {
            atomicAdd(&rowsum[m0 + tid], srow[tid]);
            atomicAdd(&mrow[m0 + tid], srowm[tid]);
        }
    } else {
        #pragma unroll
        for (int mi = 0; mi < 4; mi++) {
            int r0 = m0 + wm + mi * 16 + g;
            #pragma unroll
            for (int ni = 0; ni < 8; ni++) {
                int c = n0 + wn + ni * 8 + t4 * 2;
                float2 bc = *(const float2*)&bias[c];
                float v0 = acc[mi][ni][0] + bc.x;
                float v1 = acc[mi][ni][1] + bc.y;
                float v2 = acc[mi][ni][2] + bc.x;
                float v3 = acc[mi][ni][3] + bc.y;
                if (MODE == 0) {
                    v0 = (v0 > 0.f) ? v0 : expm1f(v0);
                    v1 = (v1 > 0.f) ? v1 : expm1f(v1);
                    v2 = (v2 > 0.f) ? v2 : expm1f(v2);
                    v3 = (v3 > 0.f) ? v3 : expm1f(v3);
                }
                *(uint32_t*)&C[(size_t)r0 * Nc + c] = bf2_pack(v0, v1);
                *(uint32_t*)&C[(size_t)(r0 + 8) * Nc + c] = bf2_pack(v2, v3);
            }
        }
    }
}

// ---------------- small utility kernels ------------------------------------
__global__ void zero_scalars_k(double* s) {
    if (threadIdx.x < 4) s[threadIdx.x] = 0.0;
}

__global__ void zero4_k(float* a, float* b, float* c, float* d) {
    int i = blockIdx.x * blockDim.x + threadIdx.x;
    if (i < N) { a[i] = 0.f; b[i] = 0.f; c[i] = 0.f; d[i] = 0.f; }
}

__global__ void conv_bf16_k(const float* __restrict__ src, __nv_bfloat16* __restrict__ dst, int n) {
    int idx = (blockIdx.x * blockDim.x + threadIdx.x) * 4;
    if (idx < n) {
        float4 v = *(const float4*)&src[idx];
        *(__nv_bfloat162*)&dst[idx] = __floats2bfloat162_rn(v.x, v.y);
        *(__nv_bfloat162*)&dst[idx + 2] = __floats2bfloat162_rn(v.z, v.w);
    }
}

// convert 4 inputs to bf16 (stacked) AND emit combined z1/z2 in one pass
__global__ void conv4_combine_k(const float* __restrict__ a, const float* __restrict__ b,
                                const float* __restrict__ c, const float* __restrict__ d,
                                const float* __restrict__ gamma,
                                __nv_bfloat16* __restrict__ dst,
                                __nv_bfloat16* __restrict__ z1, __nv_bfloat16* __restrict__ z2) {
    float gm = *gamma;
    int idx = (blockIdx.x * blockDim.x + threadIdx.x) * 4;
    if (idx < N * D) {
        float4 v0 = *(const float4*)&a[idx];
        float4 v1 = *(const float4*)&b[idx];
        float4 v2 = *(const float4*)&c[idx];
        float4 v3 = *(const float4*)&d[idx];
        __nv_bfloat16* o0 = dst + idx;
        __nv_bfloat16* o1 = dst + (size_t)N * D + idx;
        __nv_bfloat16* o2 = dst + (size_t)2 * N * D + idx;
        __nv_bfloat16* o3 = dst + (size_t)3 * N * D + idx;
        *(__nv_bfloat162*)&o0[0] = __floats2bfloat162_rn(v0.x, v0.y);
        *(__nv_bfloat162*)&o0[2] = __floats2bfloat162_rn(v0.z, v0.w);
        *(__nv_bfloat162*)&o1[0] = __floats2bfloat162_rn(v1.x, v1.y);
        *(__nv_bfloat162*)&o1[2] = __floats2bfloat162_rn(v1.z, v1.w);
        *(__nv_bfloat162*)&o2[0] = __floats2bfloat162_rn(v2.x, v2.y);
        *(__nv_bfloat162*)&o2[2] = __floats2bfloat162_rn(v2.z, v2.w);
        *(__nv_bfloat162*)&o3[0] = __floats2bfloat162_rn(v3.x, v3.y);
        *(__nv_bfloat162*)&o3[2] = __floats2bfloat162_rn(v3.z, v3.w);
        float og = 1.f - gm;
        *(__nv_bfloat162*)&z1[idx]     = __floats2bfloat162_rn(og*v0.x + gm*v1.x, og*v0.y + gm*v1.y);
        *(__nv_bfloat162*)&z1[idx + 2] = __floats2bfloat162_rn(og*v0.z + gm*v1.z, og*v0.w + gm*v1.w);
        *(__nv_bfloat162*)&z2[idx]     = __floats2bfloat162_rn(og*v2.x + gm*v3.x, og*v2.y + gm*v3.y);
        *(__nv_bfloat162*)&z2[idx + 2] = __floats2bfloat162_rn(og*v2.z + gm*v3.z, og*v2.w + gm*v3.w);
    }
}

// normalize rows in place (bf16), one warp per row, 4N rows
__global__ void normalize16_k(__nv_bfloat16* __restrict__ P) {
    int row = (blockIdx.x * blockDim.x + threadIdx.x) >> 5;
    int lane = threadIdx.x & 31;
    if (row >= 4 * N) return;
    __nv_bfloat162* p = (__nv_bfloat162*)(P + (size_t)row * D);
    float ss = 0.f;
    float2 v[16];
    #pragma unroll
    for (int u = 0; u < 16; u++) {
        v[u] = __bfloat1622float2(p[lane + u * 32]);
        ss += v[u].x * v[u].x + v[u].y * v[u].y;
    }
    #pragma unroll
    for (int o = 16; o; o >>= 1) ss += __shfl_xor_sync(0xffffffffu, ss, o);
    float inv = rsqrtf(ss);
    #pragma unroll
    for (int u = 0; u < 16; u++)
        p[lane + u * 32] = __floats2bfloat162_rn(v[u].x * inv, v[u].y * inv);
}

// ---------------- lori reduction --------------------------------------------
__global__ void lori_reduce_k(const float* __restrict__ mrow, const float* __restrict__ rowsum,
                              const float* __restrict__ mcol, const float* __restrict__ colsum,
                              double* __restrict__ target) {
    __shared__ float sm[8];
    int i = blockIdx.x * blockDim.x + threadIdx.x;
    float v = 0.f;
    if (i < N)
        v = logf(mrow[i]) - logf(rowsum[i] + 1e-8f)
          + logf(mcol[i]) - logf(colsum[i] + 1e-8f);
    #pragma unroll
    for (int o = 16; o; o >>= 1) v += __shfl_xor_sync(0xffffffffu, v, o);
    int lane = threadIdx.x & 31, w = threadIdx.x >> 5;
    if (lane == 0) sm[w] = v;
    __syncthreads();
    if (threadIdx.x < 8) {
        float t = sm[threadIdx.x];
        #pragma unroll
        for (int o = 4; o; o >>= 1) t += __shfl_xor_sync(0xffu, t, o);
        if (threadIdx.x == 0) atomicAdd(target, (double)t);
    }
}

// ---------------- InfoNCE LSE over 100 pseudo-random negatives -------------
__global__ __launch_bounds__(128)
void neg_lse_k(const __nv_bfloat16* __restrict__ z1, const __nv_bfloat16* __restrict__ z2,
               const float* __restrict__ md, float* __restrict__ lse) {
    __shared__ float2 zrow[D / 2];
    __shared__ int idxs[NUM_NEG];
    __shared__ float vals[NUM_NEG];
    int i = blockIdx.x;
    const __nv_bfloat162* zi = (const __nv_bfloat162*)(z1 + (size_t)i * D);
    for (int d = threadIdx.x; d < D / 2; d += blockDim.x)
        zrow[d] = __bfloat1622float2(zi[d]);
    if (threadIdx.x == 0) {
        const float* mr = md + (size_t)i * N;
        unsigned start = ((unsigned)i * 2654435761u) & (N - 1);
        int cnt = 0;
        for (unsigned t = 0; cnt < NUM_NEG; t++) {
            int c = (start + t * 97u) & (N - 1);
            if (mr[c] == 0.f) idxs[cnt++] = c;
        }
    }
    __syncthreads();
    int warp = threadIdx.x >> 5, lane = threadIdx.x & 31;
    for (int k = warp; k < NUM_NEG; k += 4) {
        const __nv_bfloat162* zc = (const __nv_bfloat162*)(z2 + (size_t)idxs[k] * D);
        float s = 0.f;
        #pragma unroll 4
        for (int d = lane; d < D / 2; d += 32) {
            float2 x = zrow[d];
            float2 y = __bfloat1622float2(zc[d]);
            s = fmaf(x.x, y.x, s);
            s = fmaf(x.y, y.y, s);
        }
        #pragma unroll
        for (int o = 16; o; o >>= 1) s += __shfl_xor_sync(0xffffffffu, s, o);
        if (lane == 0) vals[k] = s;
    }
    __syncthreads();
    if (threadIdx.x == 0) {
        float m = -1e30f;
        for (int k = 0; k < NUM_NEG; k++) m = fmaxf(m, vals[k]);
        float ss = 0.f;
        for (int k = 0; k < NUM_NEG; k++) ss += __expf((vals[k] - m) * 10.0f);
        lse[i] = m * 10.0f + logf(ss);   // 1/INFONCE_TAU = 10
    }
}

// ---------------- InfoNCE positive pairs (warp per row) --------------------
__global__ void inf_pairs_k(const __nv_bfloat16* __restrict__ z1, const __nv_bfloat16* __restrict__ z2,
                            const float* __restrict__ md, const float* __restrict__ lse,
                            double* __restrict__ s) {
    int warp = (blockIdx.x * blockDim.x + threadIdx.x) >> 5;
    int lane = threadIdx.x & 31;
    if (warp >= N) return;
    int i = warp;
    const float* mr = md + (size_t)i * N;
    const __nv_bfloat162* Zi = (const __nv_bfloat162*)(z1 + (size_t)i * D);
    float2 zi[16];
    #pragma unroll
    for (int u = 0; u < 16; u++) zi[u] = __bfloat1622float2(Zi[lane + u * 32]);
    float L = lse[i];
    float sum = 0.f;
    int cnt = 0;
    for (int jb = 0; jb < N; jb += 32) {
        float pv = mr[jb + lane];
        unsigned mask = __ballot_sync(0xffffffffu, pv > 0.f);
        while (mask) {
            int b = __ffs(mask) - 1;
            mask &= mask - 1;
            int j = jb + b;
            const __nv_bfloat162* Zj = (const __nv_bfloat162*)(z2 + (size_t)j * D);
            float dot = 0.f;
            #pragma unroll
            for (int u = 0; u < 16; u++) {
                float2 y = __bfloat1622float2(Zj[lane + u * 32]);
                dot = fmaf(zi[u].x, y.x, dot);
                dot = fmaf(zi[u].y, y.y, dot);
            }
            #pragma unroll
            for (int o = 16; o; o >>= 1) dot += __shfl_xor_sync(0xffffffffu, dot, o);
            float p = dot * 10.0f;
            float mx = fmaxf(p, L);
            float pp = mx + logf(__expf(p - mx) + __expf(L - mx)) - p;
            sum += pp;
            cnt++;
        }
    }
    if (lane == 0) {
        atomicAdd(&s[2], (double)sum);
        atomicAdd(&s[3], (double)cnt);
    }
}

// ---------------- finalize --------------------------------------------------
__global__ void finalize_k(float* out, const double* s) {
    double gcl = -0.5 * (s[0] + s[1]) / (double)N;
    out[0] = (float)(gcl + s[2] / s[3]);
}

// ---------------- launcher --------------------------------------------------
extern "C" void kernel_launch(void* const* d_in, const int* in_sizes, int n_in,
                              void* d_out, int out_size) {
    const float* z_mp1 = (const float*)d_in[0];
    const float* z_sc1 = (const float*)d_in[1];
    const float* pos1  = (const float*)d_in[2];
    const float* z_mp2 = (const float*)d_in[3];
    const float* z_sc2 = (const float*)d_in[4];
    const float* pos2  = (const float*)d_in[5];
    const float* md    = (const float*)d_in[6];
    const float* gamma = (const float*)d_in[7];
    const float* W1 = (const float*)d_in[8];
    const float* b1 = (const float*)d_in[9];
    const float* W2 = (const float*)d_in[10];
    const float* b2 = (const float*)d_in[11];
    float* out = (float*)d_out;

    __nv_bfloat16 *gZ, *gH, *gP, *gW1, *gW2, *gz1, *gz2;
    float *grow, *gcol, *gmr, *gmc, *glse;
    double* gs;
    cudaGetSymbolAddress((void**)&gZ, g_Zall);
    cudaGetSymbolAddress((void**)&gH, g_Hall);
    cudaGetSymbolAddress((void**)&gP, g_Pall);
    cudaGetSymbolAddress((void**)&gW1, g_W1bf);
    cudaGetSymbolAddress((void**)&gW2, g_W2bf);
    cudaGetSymbolAddress((void**)&gz1, g_z1);
    cudaGetSymbolAddress((void**)&gz2, g_z2);
    cudaGetSymbolAddress((void**)&grow, g_rowsum);
    cudaGetSymbolAddress((void**)&gcol, g_colsum);
    cudaGetSymbolAddress((void**)&gmr, g_mrow);
    cudaGetSymbolAddress((void**)&gmc, g_mcol);
    cudaGetSymbolAddress((void**)&glse, g_lse);
    cudaGetSymbolAddress((void**)&gs, g_s);

    cudaFuncSetAttribute(mm_bf16_k<0>, cudaFuncAttributeMaxDynamicSharedMemorySize, DSMEM);
    cudaFuncSetAttribute(mm_bf16_k<1>, cudaFuncAttributeMaxDynamicSharedMemorySize, DSMEM);
    cudaFuncSetAttribute(mm_bf16_k<2>, cudaFuncAttributeMaxDynamicSharedMemorySize, DSMEM);

    zero_scalars_k<<<1, 32>>>(gs);
    conv_bf16_k<<<(D * D / 4 + 255) / 256, 256>>>(W1, gW1, D * D);
    conv_bf16_k<<<(D * D / 4 + 255) / 256, 256>>>(W2, gW2, D * D);
    conv4_combine_k<<<(N * D / 4 + 255) / 256, 256>>>(z_mp1, z_sc1, z_mp2, z_sc2, gamma, gZ, gz1, gz2);

    // batched projection MLP: layer1 (ELU) then layer2, M = 16384
    dim3 gproj(D / BN, 4 * N / BM);        // (4, 128)
    mm_bf16_k<0><<<gproj, 256, DSMEM>>>(gZ, gW1, b1, gH, nullptr, nullptr, nullptr, nullptr, nullptr, D);
    mm_bf16_k<1><<<gproj, 256, DSMEM>>>(gH, gW2, b2, gP, nullptr, nullptr, nullptr, nullptr, nullptr, D);
    normalize16_k<<<4 * N / 8, 256>>>(gP);

    dim3 gsim(N / BN, N / BM);             // (16, 32)
    const float* poss[2] = {pos1, pos2};
    for (int r = 0; r < 2; r++) {
        zero4_k<<<N / 256, 256>>>(grow, gcol, gmr, gmc);
        mm_bf16_k<2><<<gsim, 256, DSMEM>>>(gP + (size_t)(2 * r) * N * D,
                                           gP + (size_t)(2 * r + 1) * N * D,
                                           nullptr, nullptr, poss[r],
                                           grow, gcol, gmr, gmc, N);
        lori_reduce_k<<<N / 256, 256>>>(gmr, grow, gmc, gcol, &gs[r]);
    }

    neg_lse_k<<<N, 128>>>(gz1, gz2, md, glse);
    inf_pairs_k<<<N / 8, 256>>>(gz1, gz2, md, glse, gs);
    finalize_k<<<1, 1>>>(out, gs);
}

// round 9
// speedup vs baseline: 1.1184x; 1.1184x over previous
#include <cuda_runtime.h>
#include <cuda_bf16.h>
#include <cstdint>
#include <math.h>

#define N 4096
#define D 1024
#define NUM_NEG 100
#define BM 128
#define BN 128
#define NT 16            // K=1024 / 64
#define STAGE_A (BM * 128)            // 16384
#define STAGE_BYTES ((BM + BN) * 128) // 32768
#define DSMEM (3 * STAGE_BYTES)       // 98304

// ---------------- scratch (device globals; no allocation allowed) ----------
__device__ __nv_bfloat16 g_Zall[4 * N * D];
__device__ __nv_bfloat16 g_Hall[4 * N * D];
__device__ __nv_bfloat16 g_Pall[4 * N * D];
__device__ __nv_bfloat16 g_W1bf[D * D];
__device__ __nv_bfloat16 g_W2bf[D * D];
__device__ __nv_bfloat16 g_z1[N * D];
__device__ __nv_bfloat16 g_z2[N * D];
__device__ float g_rowsum[N], g_colsum[N], g_mrow[N], g_mcol[N], g_lse[N];
__device__ double g_s[4];  // [0]=gcl1 logsum, [1]=gcl2 logsum, [2]=pair_sum, [3]=pair_cnt

// ---------------- helpers ---------------------------------------------------
__device__ __forceinline__ uint32_t bf2_pack(float a, float b) {
    __nv_bfloat162 t = __floats2bfloat162_rn(a, b);
    return *reinterpret_cast<uint32_t*>(&t);
}

__device__ __forceinline__ void mma16816(float* c, const uint32_t* a, const uint32_t* b) {
    asm volatile(
        "mma.sync.aligned.m16n8k16.row.col.f32.bf16.bf16.f32 "
        "{%0,%1,%2,%3}, {%4,%5,%6,%7}, {%8,%9}, {%0,%1,%2,%3};"
        : "+f"(c[0]), "+f"(c[1]), "+f"(c[2]), "+f"(c[3])
        : "r"(a[0]), "r"(a[1]), "r"(a[2]), "r"(a[3]), "r"(b[0]), "r"(b[1]));
}

__device__ __forceinline__ void ldsm4(uint32_t* r, uint32_t saddr) {
    asm volatile("ldmatrix.sync.aligned.m8n8.x4.shared.b16 {%0,%1,%2,%3}, [%4];"
                 : "=r"(r[0]), "=r"(r[1]), "=r"(r[2]), "=r"(r[3]) : "r"(saddr));
}

template <int W>
__device__ __forceinline__ void cpwait() {
    asm volatile("cp.async.wait_group %0;" :: "n"(W));
}

// swizzled byte offset inside a rows x 64 bf16 stage tile (rows of 128B, 16B chunks)
__device__ __forceinline__ uint32_t SWZ64(int r, int ch) {
    return (uint32_t)(r * 128 + ((ch ^ (r & 7)) << 4));
}

// load one 64-K stage of A(BM rows) + B(BN rows), 128 threads
__device__ __forceinline__ void ld_stage(
    const __nv_bfloat16* __restrict__ A, const __nv_bfloat16* __restrict__ B,
    int m0, int n0, int kt, uint32_t st, int tid) {
    #pragma unroll
    for (int i = 0; i < (BM * 8) / 128; i++) {
        int idx = tid + i * 128;
        int row = idx >> 3, ch = idx & 7;
        const __nv_bfloat16* g = &A[(size_t)(m0 + row) * D + kt + ch * 8];
        asm volatile("cp.async.cg.shared.global [%0], [%1], 16;"
                     :: "r"(st + SWZ64(row, ch)), "l"(g));
    }
    #pragma unroll
    for (int i = 0; i < (BN * 8) / 128; i++) {
        int idx = tid + i * 128;
        int row = idx >> 3, ch = idx & 7;
        const __nv_bfloat16* g = &B[(size_t)(n0 + row) * D + kt + ch * 8];
        asm volatile("cp.async.cg.shared.global [%0], [%1], 16;"
                     :: "r"(st + STAGE_A + SWZ64(row, ch)), "l"(g));
    }
}

// ---------------- bf16 HMMA NT GEMM (128x128 block, 64x64 per warp, 4 warps)
// C[i,j] = sum_k A[i,k]*B[j,k].  MODE 0: +bias+ELU->bf16, 1: +bias->bf16,
// 2: sim epilogue (exp(acc/0.8), rowsum/colsum + pos-masked mrow/mcol)
template <int MODE>
__global__ __launch_bounds__(128, 2)
void mm_bf16_k(const __nv_bfloat16* __restrict__ A, const __nv_bfloat16* __restrict__ B,
               const float* __restrict__ bias, __nv_bfloat16* __restrict__ C,
               const float* __restrict__ pos,
               float* __restrict__ rowsum, float* __restrict__ colsum,
               float* __restrict__ mrow, float* __restrict__ mcol, int Nc) {
    extern __shared__ __align__(16) char dsm[];
    __shared__ float srow[BM], srowm[BM];

    int tid = threadIdx.x;
    int warp = tid >> 5, lane = tid & 31;
    int g = lane >> 2, t4 = lane & 3;
    int wm = (warp >> 1) * 64;   // 2 warp-rows x 64
    int wn = (warp & 1) * 64;    // 2 warp-cols x 64
    int m0 = blockIdx.y * BM, n0 = blockIdx.x * BN;
    uint32_t sb = (uint32_t)__cvta_generic_to_shared(dsm);

    float acc[4][8][4] = {};

    ld_stage(A, B, m0, n0, 0, sb, tid);
    asm volatile("cp.async.commit_group;");
    ld_stage(A, B, m0, n0, 64, sb + STAGE_BYTES, tid);
    asm volatile("cp.async.commit_group;");

    int lr = lane & 15, lc = lane >> 4;
    for (int s = 0; s < NT; s++) {
        if (s < NT - 1) cpwait<1>(); else cpwait<0>();
        __syncthreads();
        if (s + 2 < NT) {
            ld_stage(A, B, m0, n0, (s + 2) * 64, sb + ((s + 2) % 3) * STAGE_BYTES, tid);
            asm volatile("cp.async.commit_group;");
        }
        uint32_t ab = sb + (s % 3) * STAGE_BYTES;
        uint32_t bb = ab + STAGE_A;
        #pragma unroll
        for (int ks = 0; ks < 4; ks++) {
            int ch = ks * 2 + lc;
            uint32_t a[4][4], b[4][4];
            #pragma unroll
            for (int mi = 0; mi < 4; mi++)
                ldsm4(a[mi], ab + SWZ64(wm + mi * 16 + lr, ch));
            #pragma unroll
            for (int nb = 0; nb < 4; nb++)
                ldsm4(b[nb], bb + SWZ64(wn + nb * 16 + lr, ch));
            #pragma unroll
            for (int mi = 0; mi < 4; mi++)
                #pragma unroll
                for (int ni = 0; ni < 8; ni++) {
                    uint32_t bf[2] = { b[ni >> 1][ni & 1], b[ni >> 1][(ni & 1) + 2] };
                    mma16816(acc[mi][ni], a[mi], bf);
                }
        }
    }
    __syncthreads();   // smem reuse barrier (MODE 2 epilogue overlays stage bufs)

    if (MODE == 2) {
        srow[tid] = 0.f; srowm[tid] = 0.f;
        __syncthreads();
        float rp[4][2] = {}, rpm[4][2] = {};
        #pragma unroll
        for (int mi = 0; mi < 4; mi++) {
            int r0 = m0 + wm + mi * 16 + g;
            int r1 = r0 + 8;
            #pragma unroll
            for (int ni = 0; ni < 8; ni++) {
                int c = n0 + wn + ni * 8 + t4 * 2;
                float e0 = __expf(acc[mi][ni][0] * 1.25f);   // 1/TAU
                float e1 = __expf(acc[mi][ni][1] * 1.25f);
                float e2 = __expf(acc[mi][ni][2] * 1.25f);
                float e3 = __expf(acc[mi][ni][3] * 1.25f);
                acc[mi][ni][0] = e0; acc[mi][ni][1] = e1;
                acc[mi][ni][2] = e2; acc[mi][ni][3] = e3;
                float2 p0 = *(const float2*)&pos[(size_t)r0 * N + c];
                float2 p1 = *(const float2*)&pos[(size_t)r1 * N + c];
                rp[mi][0] += e0 + e1;            rp[mi][1] += e2 + e3;
                rpm[mi][0] += e0 * p0.x + e1 * p0.y;
                rpm[mi][1] += e2 * p1.x + e3 * p1.y;
            }
        }
        #pragma unroll
        for (int mi = 0; mi < 4; mi++) {
            int r = wm + mi * 16 + g;
            atomicAdd(&srow[r], rp[mi][0]);
            atomicAdd(&srow[r + 8], rp[mi][1]);
            atomicAdd(&srowm[r], rpm[mi][0]);
            atomicAdd(&srowm[r + 8], rpm[mi][1]);
        }
        // two 32-col transpose passes: et[col_local][row_local], pitch 65
        float* et = (float*)dsm + warp * (32 * 65);
        #pragma unroll
        for (int half = 0; half < 2; half++) {
            #pragma unroll
            for (int mi = 0; mi < 4; mi++)
                #pragma unroll
                for (int nl = 0; nl < 4; nl++) {
                    int ni = half * 4 + nl;
                    #pragma unroll
                    for (int q = 0; q < 4; q++) {
                        int rl = mi * 16 + g + ((q >= 2) ? 8 : 0);
                        int cl = nl * 8 + t4 * 2 + (q & 1);
                        et[cl * 65 + rl] = acc[mi][ni][q];
                    }
                }
            __syncwarp();
            int c = n0 + wn + half * 32 + lane;
            const float4* pc = (const float4*)&pos[(size_t)c * N + m0 + wm];
            float cs = 0.f, csm = 0.f;
            #pragma unroll
            for (int q = 0; q < 16; q++) {
                float4 m4 = pc[q];
                float a0 = et[lane * 65 + q * 4 + 0];
                float a1 = et[lane * 65 + q * 4 + 1];
                float a2 = et[lane * 65 + q * 4 + 2];
                float a3 = et[lane * 65 + q * 4 + 3];
                cs  += a0 + a1 + a2 + a3;
                csm += a0 * m4.x + a1 * m4.y + a2 * m4.z + a3 * m4.w;
            }
            atomicAdd(&colsum[c], cs);
            atomicAdd(&mcol[c], csm);
            __syncwarp();
        }
        __syncthreads();
        atomicAdd(&rowsum[m0 + tid], srow[tid]);
        atomicAdd(&mrow[m0 + tid], srowm[tid]);
    } else {
        #pragma unroll
        for (int mi = 0; mi < 4; mi++) {
            int r0 = m0 + wm + mi * 16 + g;
            #pragma unroll
            for (int ni = 0; ni < 8; ni++) {
                int c = n0 + wn + ni * 8 + t4 * 2;
                float2 bc = *(const float2*)&bias[c];
                float v0 = acc[mi][ni][0] + bc.x;
                float v1 = acc[mi][ni][1] + bc.y;
                float v2 = acc[mi][ni][2] + bc.x;
                float v3 = acc[mi][ni][3] + bc.y;
                if (MODE == 0) {
                    v0 = (v0 > 0.f) ? v0 : expm1f(v0);
                    v1 = (v1 > 0.f) ? v1 : expm1f(v1);
                    v2 = (v2 > 0.f) ? v2 : expm1f(v2);
                    v3 = (v3 > 0.f) ? v3 : expm1f(v3);
                }
                *(uint32_t*)&C[(size_t)r0 * Nc + c] = bf2_pack(v0, v1);
                *(uint32_t*)&C[(size_t)(r0 + 8) * Nc + c] = bf2_pack(v2, v3);
            }
        }
    }
}

// ---------------- small utility kernels ------------------------------------
__global__ void zero_scalars_k(double* s) {
    if (threadIdx.x < 4) s[threadIdx.x] = 0.0;
}

__global__ void zero4_k(float* a, float* b, float* c, float* d) {
    int i = blockIdx.x * blockDim.x + threadIdx.x;
    if (i < N) { a[i] = 0.f; b[i] = 0.f; c[i] = 0.f; d[i] = 0.f; }
}

__global__ void conv_bf16_k(const float* __restrict__ src, __nv_bfloat16* __restrict__ dst, int n) {
    int idx = (blockIdx.x * blockDim.x + threadIdx.x) * 4;
    if (idx < n) {
        float4 v = *(const float4*)&src[idx];
        *(__nv_bfloat162*)&dst[idx] = __floats2bfloat162_rn(v.x, v.y);
        *(__nv_bfloat162*)&dst[idx + 2] = __floats2bfloat162_rn(v.z, v.w);
    }
}

// convert 4 inputs to bf16 (stacked) AND emit combined z1/z2 in one pass
__global__ void conv4_combine_k(const float* __restrict__ a, const float* __restrict__ b,
                                const float* __restrict__ c, const float* __restrict__ d,
                                const float* __restrict__ gamma,
                                __nv_bfloat16* __restrict__ dst,
                                __nv_bfloat16* __restrict__ z1, __nv_bfloat16* __restrict__ z2) {
    float gm = *gamma;
    int idx = (blockIdx.x * blockDim.x + threadIdx.x) * 4;
    if (idx < N * D) {
        float4 v0 = *(const float4*)&a[idx];
        float4 v1 = *(const float4*)&b[idx];
        float4 v2 = *(const float4*)&c[idx];
        float4 v3 = *(const float4*)&d[idx];
        __nv_bfloat16* o0 = dst + idx;
        __nv_bfloat16* o1 = dst + (size_t)N * D + idx;
        __nv_bfloat16* o2 = dst + (size_t)2 * N * D + idx;
        __nv_bfloat16* o3 = dst + (size_t)3 * N * D + idx;
        *(__nv_bfloat162*)&o0[0] = __floats2bfloat162_rn(v0.x, v0.y);
        *(__nv_bfloat162*)&o0[2] = __floats2bfloat162_rn(v0.z, v0.w);
        *(__nv_bfloat162*)&o1[0] = __floats2bfloat162_rn(v1.x, v1.y);
        *(__nv_bfloat162*)&o1[2] = __floats2bfloat162_rn(v1.z, v1.w);
        *(__nv_bfloat162*)&o2[0] = __floats2bfloat162_rn(v2.x, v2.y);
        *(__nv_bfloat162*)&o2[2] = __floats2bfloat162_rn(v2.z, v2.w);
        *(__nv_bfloat162*)&o3[0] = __floats2bfloat162_rn(v3.x, v3.y);
        *(__nv_bfloat162*)&o3[2] = __floats2bfloat162_rn(v3.z, v3.w);
        float og = 1.f - gm;
        *(__nv_bfloat162*)&z1[idx]     = __floats2bfloat162_rn(og*v0.x + gm*v1.x, og*v0.y + gm*v1.y);
        *(__nv_bfloat162*)&z1[idx + 2] = __floats2bfloat162_rn(og*v0.z + gm*v1.z, og*v0.w + gm*v1.w);
        *(__nv_bfloat162*)&z2[idx]     = __floats2bfloat162_rn(og*v2.x + gm*v3.x, og*v2.y + gm*v3.y);
        *(__nv_bfloat162*)&z2[idx + 2] = __floats2bfloat162_rn(og*v2.z + gm*v3.z, og*v2.w + gm*v3.w);
    }
}

// normalize rows in place (bf16), one warp per row, 4N rows
__global__ void normalize16_k(__nv_bfloat16* __restrict__ P) {
    int row = (blockIdx.x * blockDim.x + threadIdx.x) >> 5;
    int lane = threadIdx.x & 31;
    if (row >= 4 * N) return;
    __nv_bfloat162* p = (__nv_bfloat162*)(P + (size_t)row * D);
    float ss = 0.f;
    float2 v[16];
    #pragma unroll
    for (int u = 0; u < 16; u++) {
        v[u] = __bfloat1622float2(p[lane + u * 32]);
        ss += v[u].x * v[u].x + v[u].y * v[u].y;
    }
    #pragma unroll
    for (int o = 16; o; o >>= 1) ss += __shfl_xor_sync(0xffffffffu, ss, o);
    float inv = rsqrtf(ss);
    #pragma unroll
    for (int u = 0; u < 16; u++)
        p[lane + u * 32] = __floats2bfloat162_rn(v[u].x * inv, v[u].y * inv);
}

// ---------------- lori reduction --------------------------------------------
__global__ void lori_reduce_k(const float* __restrict__ mrow, const float* __restrict__ rowsum,
                              const float* __restrict__ mcol, const float* __restrict__ colsum,
                              double* __restrict__ target) {
    __shared__ float sm[8];
    int i = blockIdx.x * blockDim.x + threadIdx.x;
    float v = 0.f;
    if (i < N)
        v = logf(mrow[i]) - logf(rowsum[i] + 1e-8f)
          + logf(mcol[i]) - logf(colsum[i] + 1e-8f);
    #pragma unroll
    for (int o = 16; o; o >>= 1) v += __shfl_xor_sync(0xffffffffu, v, o);
    int lane = threadIdx.x & 31, w = threadIdx.x >> 5;
    if (lane == 0) sm[w] = v;
    __syncthreads();
    if (threadIdx.x < 8) {
        float t = sm[threadIdx.x];
        #pragma unroll
        for (int o = 4; o; o >>= 1) t += __shfl_xor_sync(0xffu, t, o);
        if (threadIdx.x == 0) atomicAdd(target, (double)t);
    }
}

// ---------------- InfoNCE LSE over 100 pseudo-random negatives -------------
__global__ __launch_bounds__(128)
void neg_lse_k(const __nv_bfloat16* __restrict__ z1, const __nv_bfloat16* __restrict__ z2,
               const float* __restrict__ md, float* __restrict__ lse) {
    __shared__ float2 zrow[D / 2];
    __shared__ int idxs[NUM_NEG];
    __shared__ float vals[NUM_NEG];
    int i = blockIdx.x;
    const __nv_bfloat162* zi = (const __nv_bfloat162*)(z1 + (size_t)i * D);
    for (int d = threadIdx.x; d < D / 2; d += blockDim.x)
        zrow[d] = __bfloat1622float2(zi[d]);
    if (threadIdx.x == 0) {
        const float* mr = md + (size_t)i * N;
        unsigned start = ((unsigned)i * 2654435761u) & (N - 1);
        int cnt = 0;
        for (unsigned t = 0; cnt < NUM_NEG; t++) {
            int c = (start + t * 97u) & (N - 1);
            if (mr[c] == 0.f) idxs[cnt++] = c;
        }
    }
    __syncthreads();
    int warp = threadIdx.x >> 5, lane = threadIdx.x & 31;
    for (int k = warp; k < NUM_NEG; k += 4) {
        const __nv_bfloat162* zc = (const __nv_bfloat162*)(z2 + (size_t)idxs[k] * D);
        float s = 0.f;
        #pragma unroll 4
        for (int d = lane; d < D / 2; d += 32) {
            float2 x = zrow[d];
            float2 y = __bfloat1622float2(zc[d]);
            s = fmaf(x.x, y.x, s);
            s = fmaf(x.y, y.y, s);
        }
        #pragma unroll
        for (int o = 16; o; o >>= 1) s += __shfl_xor_sync(0xffffffffu, s, o);
        if (lane == 0) vals[k] = s;
    }
    __syncthreads();
    if (threadIdx.x == 0) {
        float m = -1e30f;
        for (int k = 0; k < NUM_NEG; k++) m = fmaxf(m, vals[k]);
        float ss = 0.f;
        for (int k = 0; k < NUM_NEG; k++) ss += __expf((vals[k] - m) * 10.0f);
        lse[i] = m * 10.0f + logf(ss);   // 1/INFONCE_TAU = 10
    }
}

// ---------------- InfoNCE positive pairs (warp per row) --------------------
__global__ void inf_pairs_k(const __nv_bfloat16* __restrict__ z1, const __nv_bfloat16* __restrict__ z2,
                            const float* __restrict__ md, const float* __restrict__ lse,
                            double* __restrict__ s) {
    int warp = (blockIdx.x * blockDim.x + threadIdx.x) >> 5;
    int lane = threadIdx.x & 31;
    if (warp >= N) return;
    int i = warp;
    const float* mr = md + (size_t)i * N;
    const __nv_bfloat162* Zi = (const __nv_bfloat162*)(z1 + (size_t)i * D);
    float2 zi[16];
    #pragma unroll
    for (int u = 0; u < 16; u++) zi[u] = __bfloat1622float2(Zi[lane + u * 32]);
    float L = lse[i];
    float sum = 0.f;
    int cnt = 0;
    for (int jb = 0; jb < N; jb += 32) {
        float pv = mr[jb + lane];
        unsigned mask = __ballot_sync(0xffffffffu, pv > 0.f);
        while (mask) {
            int b = __ffs(mask) - 1;
            mask &= mask - 1;
            int j = jb + b;
            const __nv_bfloat162* Zj = (const __nv_bfloat162*)(z2 + (size_t)j * D);
            float dot = 0.f;
            #pragma unroll
            for (int u = 0; u < 16; u++) {
                float2 y = __bfloat1622float2(Zj[lane + u * 32]);
                dot = fmaf(zi[u].x, y.x, dot);
                dot = fmaf(zi[u].y, y.y, dot);
            }
            #pragma unroll
            for (int o = 16; o; o >>= 1) dot += __shfl_xor_sync(0xffffffffu, dot, o);
            float p = dot * 10.0f;
            float mx = fmaxf(p, L);
            float pp = mx + logf(__expf(p - mx) + __expf(L - mx)) - p;
            sum += pp;
            cnt++;
        }
    }
    if (lane == 0) {
        atomicAdd(&s[2], (double)sum);
        atomicAdd(&s[3], (double)cnt);
    }
}

// ---------------- finalize --------------------------------------------------
__global__ void finalize_k(float* out, const double* s) {
    double gcl = -0.5 * (s[0] + s[1]) / (double)N;
    out[0] = (float)(gcl + s[2] / s[3]);
}

// ---------------- launcher --------------------------------------------------
extern "C" void kernel_launch(void* const* d_in, const int* in_sizes, int n_in,
                              void* d_out, int out_size) {
    const float* z_mp1 = (const float*)d_in[0];
    const float* z_sc1 = (const float*)d_in[1];
    const float* pos1  = (const float*)d_in[2];
    const float* z_mp2 = (const float*)d_in[3];
    const float* z_sc2 = (const float*)d_in[4];
    const float* pos2  = (const float*)d_in[5];
    const float* md    = (const float*)d_in[6];
    const float* gamma = (const float*)d_in[7];
    const float* W1 = (const float*)d_in[8];
    const float* b1 = (const float*)d_in[9];
    const float* W2 = (const float*)d_in[10];
    const float* b2 = (const float*)d_in[11];
    float* out = (float*)d_out;

    __nv_bfloat16 *gZ, *gH, *gP, *gW1, *gW2, *gz1, *gz2;
    float *grow, *gcol, *gmr, *gmc, *glse;
    double* gs;
    cudaGetSymbolAddress((void**)&gZ, g_Zall);
    cudaGetSymbolAddress((void**)&gH, g_Hall);
    cudaGetSymbolAddress((void**)&gP, g_Pall);
    cudaGetSymbolAddress((void**)&gW1, g_W1bf);
    cudaGetSymbolAddress((void**)&gW2, g_W2bf);
    cudaGetSymbolAddress((void**)&gz1, g_z1);
    cudaGetSymbolAddress((void**)&gz2, g_z2);
    cudaGetSymbolAddress((void**)&grow, g_rowsum);
    cudaGetSymbolAddress((void**)&gcol, g_colsum);
    cudaGetSymbolAddress((void**)&gmr, g_mrow);
    cudaGetSymbolAddress((void**)&gmc, g_mcol);
    cudaGetSymbolAddress((void**)&glse, g_lse);
    cudaGetSymbolAddress((void**)&gs, g_s);

    cudaFuncSetAttribute(mm_bf16_k<0>, cudaFuncAttributeMaxDynamicSharedMemorySize, DSMEM);
    cudaFuncSetAttribute(mm_bf16_k<1>, cudaFuncAttributeMaxDynamicSharedMemorySize, DSMEM);
    cudaFuncSetAttribute(mm_bf16_k<2>, cudaFuncAttributeMaxDynamicSharedMemorySize, DSMEM);

    zero_scalars_k<<<1, 32>>>(gs);
    conv_bf16_k<<<(D * D / 4 + 255) / 256, 256>>>(W1, gW1, D * D);
    conv_bf16_k<<<(D * D / 4 + 255) / 256, 256>>>(W2, gW2, D * D);
    conv4_combine_k<<<(N * D / 4 + 255) / 256, 256>>>(z_mp1, z_sc1, z_mp2, z_sc2, gamma, gZ, gz1, gz2);

    // batched projection MLP: layer1 (ELU) then layer2, M = 16384
    dim3 gproj(D / BN, 4 * N / BM);        // (8, 128)
    mm_bf16_k<0><<<gproj, 128, DSMEM>>>(gZ, gW1, b1, gH, nullptr, nullptr, nullptr, nullptr, nullptr, D);
    mm_bf16_k<1><<<gproj, 128, DSMEM>>>(gH, gW2, b2, gP, nullptr, nullptr, nullptr, nullptr, nullptr, D);
    normalize16_k<<<4 * N / 8, 256>>>(gP);

    dim3 gsim(N / BN, N / BM);             // (32, 32)
    const float* poss[2] = {pos1, pos2};
    for (int r = 0; r < 2; r++) {
        zero4_k<<<N / 256, 256>>>(grow, gcol, gmr, gmc);
        mm_bf16_k<2><<<gsim, 128, DSMEM>>>(gP + (size_t)(2 * r) * N * D,
                                           gP + (size_t)(2 * r + 1) * N * D,
                                           nullptr, nullptr, poss[r],
                                           grow, gcol, gmr, gmc, N);
        lori_reduce_k<<<N / 256, 256>>>(gmr, grow, gmc, gcol, &gs[r]);
    }

    neg_lse_k<<<N, 128>>>(gz1, gz2, md, glse);
    inf_pairs_k<<<N / 8, 256>>>(gz1, gz2, md, glse, gs);
    finalize_k<<<1, 1>>>(out, gs);
}